// round 2
// baseline (speedup 1.0000x reference)
#include <cuda_runtime.h>

#define BS_   32
#define N_    1024
#define D_    1024
#define ROWS  (BS_ * N_)   // 32768

// ---- scratch (device globals; no allocation allowed) ----
__device__ float g_q[ROWS];
__device__ float g_k[ROWS];
__device__ float g_kmax[BS_];
__device__ float g_kmin[BS_];
__device__ float g_V[(size_t)D_ * ROWS];   // V[o, b*1024+n], row stride ROWS (128 MB)

// ============================================================
// Kernel 1: q = x·Wq + bq, k = x·Wk + bk   (one warp per row)
// ============================================================
__global__ __launch_bounds__(256) void qk_kernel(
    const float* __restrict__ x,
    const float* __restrict__ Wq, const float* __restrict__ Wk,
    const float* __restrict__ bq, const float* __restrict__ bk)
{
    int warp = threadIdx.x >> 5;
    int lane = threadIdx.x & 31;
    int row  = blockIdx.x * 8 + warp;
    const float* xr = x + (size_t)row * D_;

    float aq = 0.f, ak = 0.f;
#pragma unroll
    for (int i = 0; i < 8; i++) {
        int d = lane * 4 + i * 128;
        float4 xv = *(const float4*)(xr + d);
        float4 wq = *(const float4*)(Wq + d);
        float4 wk = *(const float4*)(Wk + d);
        aq += xv.x * wq.x + xv.y * wq.y + xv.z * wq.z + xv.w * wq.w;
        ak += xv.x * wk.x + xv.y * wk.y + xv.z * wk.z + xv.w * wk.w;
    }
#pragma unroll
    for (int o = 16; o; o >>= 1) {
        aq += __shfl_xor_sync(0xFFFFFFFFu, aq, o);
        ak += __shfl_xor_sync(0xFFFFFFFFu, ak, o);
    }
    if (lane == 0) {
        g_q[row] = aq + bq[0];
        g_k[row] = ak + bk[0];
    }
}

// ============================================================
// Kernel 2: per-batch max/min of k (for softmax stabilization)
// ============================================================
__global__ __launch_bounds__(256) void kminmax_kernel()
{
    __shared__ float smx[256], smn[256];
    int b = blockIdx.x;
    int tid = threadIdx.x;
    float4 kv = *(const float4*)&g_k[b * N_ + tid * 4];
    float mx = fmaxf(fmaxf(kv.x, kv.y), fmaxf(kv.z, kv.w));
    float mn = fminf(fminf(kv.x, kv.y), fminf(kv.z, kv.w));
    smx[tid] = mx; smn[tid] = mn;
    __syncthreads();
    for (int s = 128; s; s >>= 1) {
        if (tid < s) {
            smx[tid] = fmaxf(smx[tid], smx[tid + s]);
            smn[tid] = fminf(smn[tid], smn[tid + s]);
        }
        __syncthreads();
    }
    if (tid == 0) { g_kmax[b] = smx[0]; g_kmin[b] = smn[0]; }
}

// ============================================================
// Kernel 3: attention row softmax (rank-1 energy => trivial max)
//   A[b,n,m] = exp(q_n*k_m - M_n) / sum_m exp(...)
//   one block per row, 256 threads x 4 elements
// ============================================================
__global__ __launch_bounds__(256) void softmax_kernel(float* __restrict__ att)
{
    __shared__ float red[8];
    int row = blockIdx.x;
    int b   = row >> 10;
    int tid = threadIdx.x;
    int lane = tid & 31, warp = tid >> 5;

    float q  = g_q[row];
    float mx = (q >= 0.f) ? q * g_kmax[b] : q * g_kmin[b];

    float4 kv = *(const float4*)&g_k[b * N_ + tid * 4];
    float e0 = __expf(fmaf(q, kv.x, -mx));
    float e1 = __expf(fmaf(q, kv.y, -mx));
    float e2 = __expf(fmaf(q, kv.z, -mx));
    float e3 = __expf(fmaf(q, kv.w, -mx));
    float s = e0 + e1 + e2 + e3;

#pragma unroll
    for (int o = 16; o; o >>= 1) s += __shfl_xor_sync(0xFFFFFFFFu, s, o);
    if (lane == 0) red[warp] = s;
    __syncthreads();
    if (warp == 0) {
        float t = (lane < 8) ? red[lane] : 0.f;
#pragma unroll
        for (int o = 4; o; o >>= 1) t += __shfl_xor_sync(0xFFFFFFFFu, t, o);
        if (lane == 0) red[0] = t;
    }
    __syncthreads();
    float inv = 1.f / red[0];

    float4 o4 = make_float4(e0 * inv, e1 * inv, e2 * inv, e3 * inv);
    *(float4*)&att[(size_t)row * N_ + tid * 4] = o4;
}

// ============================================================
// GEMM1 (NT + bias):  V[m, n] = sum_k Wv[m,k] * x[n,k] + bv[m]
//   M=1024, N=32768, K=1024. 128x128x16 tile, 256 thr, 8x8/thread.
// ============================================================
__global__ __launch_bounds__(256) void gemm1_kernel(
    const float* __restrict__ A,      // Wv, lda=1024
    const float* __restrict__ B,      // x,  ldb=1024 (B[n,k])
    const float* __restrict__ bias)   // bv
{
    constexpr int LDA = 1024, LDB = 1024, LDC = ROWS, K = 1024;
    __shared__ float As[16][132];
    __shared__ float Bs[16][132];

    int tid = threadIdx.x;
    int bm = blockIdx.y * 128;
    int bn = blockIdx.x * 128;

    int lrow = tid >> 2;          // 0..63
    int lcol = (tid & 3) << 2;    // 0,4,8,12
    const float* Ag = A + (size_t)(bm + lrow) * LDA + lcol;
    const float* Bg = B + (size_t)(bn + lrow) * LDB + lcol;

    int ty = tid >> 4, tx = tid & 15;
    float acc[8][8] = {};

    for (int k0 = 0; k0 < K; k0 += 16) {
#pragma unroll
        for (int p = 0; p < 2; p++) {
            int r = lrow + p * 64;
            float4 va = *(const float4*)(Ag + k0 + (size_t)p * 64 * LDA);
            float4 vb = *(const float4*)(Bg + k0 + (size_t)p * 64 * LDB);
            As[lcol + 0][r] = va.x; As[lcol + 1][r] = va.y;
            As[lcol + 2][r] = va.z; As[lcol + 3][r] = va.w;
            Bs[lcol + 0][r] = vb.x; Bs[lcol + 1][r] = vb.y;
            Bs[lcol + 2][r] = vb.z; Bs[lcol + 3][r] = vb.w;
        }
        __syncthreads();
#pragma unroll
        for (int k = 0; k < 16; k++) {
            float4 a0 = *(const float4*)&As[k][ty * 4];
            float4 a1 = *(const float4*)&As[k][64 + ty * 4];
            float4 b0 = *(const float4*)&Bs[k][tx * 4];
            float4 b1 = *(const float4*)&Bs[k][64 + tx * 4];
            float af[8] = {a0.x, a0.y, a0.z, a0.w, a1.x, a1.y, a1.z, a1.w};
            float bf[8] = {b0.x, b0.y, b0.z, b0.w, b1.x, b1.y, b1.z, b1.w};
#pragma unroll
            for (int i = 0; i < 8; i++)
#pragma unroll
                for (int j = 0; j < 8; j++)
                    acc[i][j] = fmaf(af[i], bf[j], acc[i][j]);
        }
        __syncthreads();
    }

#pragma unroll
    for (int i = 0; i < 8; i++) {
        int rm = bm + ((i < 4) ? (ty * 4 + i) : (64 + ty * 4 + i - 4));
        float bia = bias[rm];
        float4 c0 = make_float4(acc[i][0] + bia, acc[i][1] + bia,
                                acc[i][2] + bia, acc[i][3] + bia);
        float4 c1 = make_float4(acc[i][4] + bia, acc[i][5] + bia,
                                acc[i][6] + bia, acc[i][7] + bia);
        *(float4*)&g_V[(size_t)rm * LDC + bn + tx * 4]      = c0;
        *(float4*)&g_V[(size_t)rm * LDC + bn + 64 + tx * 4] = c1;
    }
}

// ============================================================
// GEMM2 (NN, batched): out[b][m, n] = sum_k V[m, b*1024+k] * A[b][k, n]
//   per batch: M=1024, N=1024, K=1024
// ============================================================
__global__ __launch_bounds__(256) void gemm2_kernel(
    const float* __restrict__ att, float* __restrict__ out)
{
    constexpr int LDA = ROWS, LDB = 1024, LDC = 1024, K = 1024;
    int b = blockIdx.z;
    const float* A = g_V + (size_t)b * 1024;              // A[m,k], lda=ROWS
    const float* B = att + (size_t)b * N_ * N_;           // B[k,n], ldb=1024
    float*       C = out + (size_t)b * D_ * N_;           // C[m,n], ldc=1024

    __shared__ float As[16][132];
    __shared__ float Bs[16][132];

    int tid = threadIdx.x;
    int bm = blockIdx.y * 128;
    int bn = blockIdx.x * 128;

    int lrow = tid >> 2;          // A-load: 0..63
    int lcol = (tid & 3) << 2;
    const float* Ag = A + (size_t)(bm + lrow) * LDA + lcol;

    int brow = tid >> 5;          // B-load: 0..7
    int bcol = (tid & 31) << 2;   // 0..124
    const float* Bg = B + (size_t)brow * LDB + bn + bcol;

    int ty = tid >> 4, tx = tid & 15;
    float acc[8][8] = {};

    for (int k0 = 0; k0 < K; k0 += 16) {
#pragma unroll
        for (int p = 0; p < 2; p++) {
            int r = lrow + p * 64;
            float4 va = *(const float4*)(Ag + k0 + (size_t)p * 64 * LDA);
            As[lcol + 0][r] = va.x; As[lcol + 1][r] = va.y;
            As[lcol + 2][r] = va.z; As[lcol + 3][r] = va.w;
            float4 vb = *(const float4*)(Bg + (size_t)(k0 + p * 8) * LDB);
            *(float4*)&Bs[brow + p * 8][bcol] = vb;
        }
        __syncthreads();
#pragma unroll
        for (int k = 0; k < 16; k++) {
            float4 a0 = *(const float4*)&As[k][ty * 4];
            float4 a1 = *(const float4*)&As[k][64 + ty * 4];
            float4 b0 = *(const float4*)&Bs[k][tx * 4];
            float4 b1 = *(const float4*)&Bs[k][64 + tx * 4];
            float af[8] = {a0.x, a0.y, a0.z, a0.w, a1.x, a1.y, a1.z, a1.w};
            float bf[8] = {b0.x, b0.y, b0.z, b0.w, b1.x, b1.y, b1.z, b1.w};
#pragma unroll
            for (int i = 0; i < 8; i++)
#pragma unroll
                for (int j = 0; j < 8; j++)
                    acc[i][j] = fmaf(af[i], bf[j], acc[i][j]);
        }
        __syncthreads();
    }

#pragma unroll
    for (int i = 0; i < 8; i++) {
        int rm = bm + ((i < 4) ? (ty * 4 + i) : (64 + ty * 4 + i - 4));
        float4 c0 = make_float4(acc[i][0], acc[i][1], acc[i][2], acc[i][3]);
        float4 c1 = make_float4(acc[i][4], acc[i][5], acc[i][6], acc[i][7]);
        *(float4*)&C[(size_t)rm * LDC + bn + tx * 4]      = c0;
        *(float4*)&C[(size_t)rm * LDC + bn + 64 + tx * 4] = c1;
    }
}

// ============================================================
extern "C" void kernel_launch(void* const* d_in, const int* in_sizes, int n_in,
                              void* d_out, int out_size)
{
    const float* x  = (const float*)d_in[0];
    const float* Wq = (const float*)d_in[1];
    const float* bq = (const float*)d_in[2];
    const float* Wk = (const float*)d_in[3];
    const float* bk = (const float*)d_in[4];
    const float* Wv = (const float*)d_in[5];
    const float* bv = (const float*)d_in[6];

    float* out = (float*)d_out;                       // (bs, d, n) raw layout
    float* att = out + (size_t)BS_ * N_ * D_;         // (bs, n, n)

    qk_kernel<<<ROWS / 8, 256>>>(x, Wq, Wk, bq, bk);
    kminmax_kernel<<<BS_, 256>>>();
    softmax_kernel<<<ROWS, 256>>>(att);

    dim3 g1(ROWS / 128, D_ / 128);       // (256, 8)
    gemm1_kernel<<<g1, 256>>>(Wv, x, bv);

    dim3 g2(N_ / 128, D_ / 128, BS_);    // (8, 8, 32)
    gemm2_kernel<<<g2, 256>>>(att, out);
}

// round 4
// speedup vs baseline: 2.6132x; 2.6132x over previous
#include <cuda_runtime.h>
#include <cstdint>

#define BS_   32
#define N_    1024
#define D_    1024
#define ROWS  (BS_ * N_)   // 32768

// ---- scratch (device globals; no allocation allowed) ----
__device__ float g_q[ROWS];
__device__ float g_k[ROWS];
__device__ float g_kmax[BS_];
__device__ float g_kmin[BS_];
__device__ float g_V[(size_t)D_ * ROWS];     // V[o][b*1024+n], ld=ROWS (tf32-rounded)
__device__ float g_attT[(size_t)ROWS * N_];  // attT[b*1024+m][n] (tf32-rounded)
__device__ float g_xr[(size_t)ROWS * D_];    // tf32-rounded x
__device__ float g_Wvr[(size_t)D_ * D_];     // tf32-rounded Wv

// ============================================================
// helpers
// ============================================================
__device__ __forceinline__ uint32_t smem_u32(const void* p) {
    uint32_t a;
    asm("{ .reg .u64 t; cvta.to.shared.u64 t, %1; cvt.u32.u64 %0, t; }" : "=r"(a) : "l"(p));
    return a;
}
__device__ __forceinline__ float f2tf32(float f) {
    uint32_t r;
    asm("cvt.rna.tf32.f32 %0, %1;" : "=r"(r) : "f"(f));
    return __uint_as_float(r);
}
#define CP_ASYNC16(smem, gptr) \
    asm volatile("cp.async.cg.shared.global [%0], [%1], 16;" :: "r"(smem), "l"(gptr))
#define CP_COMMIT() asm volatile("cp.async.commit_group;" ::: "memory")
#define CP_WAIT(n)  asm volatile("cp.async.wait_group %0;" :: "n"(n) : "memory")

__device__ __forceinline__ void mma_tf32(float c[4],
    uint32_t a0, uint32_t a1, uint32_t a2, uint32_t a3, uint32_t b0, uint32_t b1)
{
    asm volatile(
        "mma.sync.aligned.m16n8k8.row.col.f32.tf32.tf32.f32 "
        "{%0,%1,%2,%3}, {%4,%5,%6,%7}, {%8,%9}, {%0,%1,%2,%3};"
        : "+f"(c[0]), "+f"(c[1]), "+f"(c[2]), "+f"(c[3])
        : "r"(a0), "r"(a1), "r"(a2), "r"(a3), "r"(b0), "r"(b1));
}

// ============================================================
// Kernel 1: q/k dot products + write tf32-rounded copy of x
// ============================================================
__global__ __launch_bounds__(256) void qk_kernel(
    const float* __restrict__ x,
    const float* __restrict__ Wq, const float* __restrict__ Wk,
    const float* __restrict__ bq, const float* __restrict__ bk)
{
    int warp = threadIdx.x >> 5;
    int lane = threadIdx.x & 31;
    int row  = blockIdx.x * 8 + warp;
    const float* xr = x + (size_t)row * D_;
    float* xo = g_xr + (size_t)row * D_;

    float aq = 0.f, ak = 0.f;
#pragma unroll
    for (int i = 0; i < 8; i++) {
        int d = lane * 4 + i * 128;
        float4 xv = *(const float4*)(xr + d);
        float4 wq = *(const float4*)(Wq + d);
        float4 wk = *(const float4*)(Wk + d);
        aq += xv.x * wq.x + xv.y * wq.y + xv.z * wq.z + xv.w * wq.w;
        ak += xv.x * wk.x + xv.y * wk.y + xv.z * wk.z + xv.w * wk.w;
        float4 xt = make_float4(f2tf32(xv.x), f2tf32(xv.y), f2tf32(xv.z), f2tf32(xv.w));
        *(float4*)(xo + d) = xt;
    }
#pragma unroll
    for (int o = 16; o; o >>= 1) {
        aq += __shfl_xor_sync(0xFFFFFFFFu, aq, o);
        ak += __shfl_xor_sync(0xFFFFFFFFu, ak, o);
    }
    if (lane == 0) {
        g_q[row] = aq + bq[0];
        g_k[row] = ak + bk[0];
    }
}

// ============================================================
// Kernel 1b: tf32-round Wv
// ============================================================
__global__ __launch_bounds__(256) void round_wv_kernel(const float* __restrict__ Wv)
{
    int i = (blockIdx.x * 256 + threadIdx.x) * 4;
    float4 v = *(const float4*)(Wv + i);
    *(float4*)(g_Wvr + i) =
        make_float4(f2tf32(v.x), f2tf32(v.y), f2tf32(v.z), f2tf32(v.w));
}

// ============================================================
// Kernel 2: per-batch max/min of k
// ============================================================
__global__ __launch_bounds__(256) void kminmax_kernel()
{
    __shared__ float smx[256], smn[256];
    int b = blockIdx.x;
    int tid = threadIdx.x;
    float4 kv = *(const float4*)&g_k[b * N_ + tid * 4];
    float mx = fmaxf(fmaxf(kv.x, kv.y), fmaxf(kv.z, kv.w));
    float mn = fminf(fminf(kv.x, kv.y), fminf(kv.z, kv.w));
    smx[tid] = mx; smn[tid] = mn;
    __syncthreads();
    for (int s = 128; s; s >>= 1) {
        if (tid < s) {
            smx[tid] = fmaxf(smx[tid], smx[tid + s]);
            smn[tid] = fminf(smn[tid], smn[tid + s]);
        }
        __syncthreads();
    }
    if (tid == 0) { g_kmax[b] = smx[0]; g_kmin[b] = smn[0]; }
}

// ============================================================
// Kernel 3: row softmax of rank-1 energy (writes att = output)
// ============================================================
__global__ __launch_bounds__(256) void softmax_kernel(float* __restrict__ att)
{
    __shared__ float red[8];
    int row = blockIdx.x;
    int b   = row >> 10;
    int tid = threadIdx.x;
    int lane = tid & 31, warp = tid >> 5;

    float q  = g_q[row];
    float mx = (q >= 0.f) ? q * g_kmax[b] : q * g_kmin[b];

    float4 kv = *(const float4*)&g_k[b * N_ + tid * 4];
    float e0 = __expf(fmaf(q, kv.x, -mx));
    float e1 = __expf(fmaf(q, kv.y, -mx));
    float e2 = __expf(fmaf(q, kv.z, -mx));
    float e3 = __expf(fmaf(q, kv.w, -mx));
    float s = e0 + e1 + e2 + e3;

#pragma unroll
    for (int o = 16; o; o >>= 1) s += __shfl_xor_sync(0xFFFFFFFFu, s, o);
    if (lane == 0) red[warp] = s;
    __syncthreads();
    if (warp == 0) {
        float t = (lane < 8) ? red[lane] : 0.f;
#pragma unroll
        for (int o = 4; o; o >>= 1) t += __shfl_xor_sync(0xFFFFFFFFu, t, o);
        if (lane == 0) red[0] = t;
    }
    __syncthreads();
    float inv = 1.f / red[0];

    *(float4*)&att[(size_t)row * N_ + tid * 4] =
        make_float4(e0 * inv, e1 * inv, e2 * inv, e3 * inv);
}

// ============================================================
// Kernel 4: transpose att -> attT (tf32-rounded)
// ============================================================
__global__ __launch_bounds__(256) void transpose_kernel(const float* __restrict__ att)
{
    __shared__ float t[32][33];
    int b = blockIdx.z;
    int x0 = blockIdx.x * 32, y0 = blockIdx.y * 32;
    int tx = threadIdx.x & 31, ty = threadIdx.x >> 5;
    const float* src = att + (size_t)b * N_ * N_;
    float* dst = g_attT + (size_t)b * N_ * N_;
#pragma unroll
    for (int i = 0; i < 4; i++)
        t[ty + i * 8][tx] = src[(size_t)(y0 + ty + i * 8) * N_ + x0 + tx];
    __syncthreads();
#pragma unroll
    for (int i = 0; i < 4; i++)
        dst[(size_t)(x0 + ty + i * 8) * N_ + y0 + tx] = f2tf32(t[tx][ty + i * 8]);
}

// ============================================================
// tf32 mma.sync GEMM: C[m,n] = sum_k A[m,k]*B[n,k] (+bias[m])
//   BM=BN=128, BK=16, 256 thr, warp grid 2x4, warp tile 64x32
// ============================================================
__global__ __launch_bounds__(256) void mm_tf32_kernel(
    const float* __restrict__ A, int lda, size_t aOff,
    const float* __restrict__ B, int ldb, size_t bOff,
    float* __restrict__ C, int ldc, size_t cOff,
    const float* __restrict__ bias, int roundC)
{
    __shared__ float As[2][128][20];
    __shared__ float Bs[2][128][20];

    const int tid = threadIdx.x;
    const int wid = tid >> 5, lane = tid & 31;
    const int tq = lane >> 2, tr = lane & 3;
    const int wm = (wid & 1) * 64, wn = (wid >> 1) * 32;
    const int m0 = blockIdx.y * 128, n0 = blockIdx.x * 128, b = blockIdx.z;

    const float* Ab = A + (size_t)b * aOff;
    const float* Bb = B + (size_t)b * bOff;
    float*       Cb = C + (size_t)b * cOff;

    const int lrow = tid >> 2;            // 0..63
    const int lcol = (tid & 3) << 2;      // 0,4,8,12
    const float* Ag = Ab + (size_t)(m0 + lrow) * lda + lcol;
    const float* Bg = Bb + (size_t)(n0 + lrow) * ldb + lcol;

    uint32_t sA0 = smem_u32(&As[0][lrow][lcol]);
    uint32_t sA1 = smem_u32(&As[0][lrow + 64][lcol]);
    uint32_t sB0 = smem_u32(&Bs[0][lrow][lcol]);
    uint32_t sB1 = smem_u32(&Bs[0][lrow + 64][lcol]);
    const uint32_t stg = 128 * 20 * 4;    // stage stride in bytes
    const size_t a64 = (size_t)64 * lda, b64 = (size_t)64 * ldb;

    float c[4][4][4] = {};

    // prologue: stage 0
    CP_ASYNC16(sA0, Ag);  CP_ASYNC16(sA1, Ag + a64);
    CP_ASYNC16(sB0, Bg);  CP_ASYNC16(sB1, Bg + b64);
    CP_COMMIT();

#pragma unroll 1
    for (int it = 0; it < 64; ++it) {
        int s = it & 1;
        if (it < 63) {
            int ns = s ^ 1;
            const float* Agn = Ag + (it + 1) * 16;
            const float* Bgn = Bg + (it + 1) * 16;
            CP_ASYNC16(sA0 + ns * stg, Agn);  CP_ASYNC16(sA1 + ns * stg, Agn + a64);
            CP_ASYNC16(sB0 + ns * stg, Bgn);  CP_ASYNC16(sB1 + ns * stg, Bgn + b64);
            CP_COMMIT();
            CP_WAIT(1);
        } else {
            CP_WAIT(0);
        }
        __syncthreads();

#pragma unroll
        for (int ks = 0; ks < 16; ks += 8) {
            uint32_t a[4][4], bb[4][2];
#pragma unroll
            for (int i = 0; i < 4; i++) {
                a[i][0] = __float_as_uint(As[s][wm + i * 16 + tq][ks + tr]);
                a[i][1] = __float_as_uint(As[s][wm + i * 16 + tq + 8][ks + tr]);
                a[i][2] = __float_as_uint(As[s][wm + i * 16 + tq][ks + tr + 4]);
                a[i][3] = __float_as_uint(As[s][wm + i * 16 + tq + 8][ks + tr + 4]);
            }
#pragma unroll
            for (int j = 0; j < 4; j++) {
                bb[j][0] = __float_as_uint(Bs[s][wn + j * 8 + tq][ks + tr]);
                bb[j][1] = __float_as_uint(Bs[s][wn + j * 8 + tq][ks + tr + 4]);
            }
#pragma unroll
            for (int i = 0; i < 4; i++)
#pragma unroll
                for (int j = 0; j < 4; j++)
                    mma_tf32(c[i][j], a[i][0], a[i][1], a[i][2], a[i][3],
                             bb[j][0], bb[j][1]);
        }
        __syncthreads();
    }

    // epilogue
#pragma unroll
    for (int i = 0; i < 4; i++) {
        int r0 = m0 + wm + i * 16 + tq;
        int r1 = r0 + 8;
        float bi0 = bias ? bias[r0] : 0.f;
        float bi1 = bias ? bias[r1] : 0.f;
#pragma unroll
        for (int j = 0; j < 4; j++) {
            int col = n0 + wn + j * 8 + tr * 2;
            float2 v0 = make_float2(c[i][j][0] + bi0, c[i][j][1] + bi0);
            float2 v1 = make_float2(c[i][j][2] + bi1, c[i][j][3] + bi1);
            if (roundC) {
                v0.x = f2tf32(v0.x); v0.y = f2tf32(v0.y);
                v1.x = f2tf32(v1.x); v1.y = f2tf32(v1.y);
            }
            *(float2*)(Cb + (size_t)r0 * ldc + col) = v0;
            *(float2*)(Cb + (size_t)r1 * ldc + col) = v1;
        }
    }
}

// ============================================================
extern "C" void kernel_launch(void* const* d_in, const int* in_sizes, int n_in,
                              void* d_out, int out_size)
{
    const float* x  = (const float*)d_in[0];
    const float* Wq = (const float*)d_in[1];
    const float* bq = (const float*)d_in[2];
    const float* Wk = (const float*)d_in[3];
    const float* bk = (const float*)d_in[4];
    const float* Wv = (const float*)d_in[5];
    const float* bv = (const float*)d_in[6];

    float* out = (float*)d_out;                   // (bs, d, n) raw layout
    float* att = out + (size_t)BS_ * N_ * D_;     // (bs, n, n)

    void *pV, *pAT, *pXR, *pWV;
    cudaGetSymbolAddress(&pV, g_V);
    cudaGetSymbolAddress(&pAT, g_attT);
    cudaGetSymbolAddress(&pXR, g_xr);
    cudaGetSymbolAddress(&pWV, g_Wvr);

    qk_kernel<<<ROWS / 8, 256>>>(x, Wq, Wk, bq, bk);
    round_wv_kernel<<<(D_ * D_) / 1024, 256>>>(Wv);
    kminmax_kernel<<<BS_, 256>>>();
    softmax_kernel<<<ROWS, 256>>>(att);
    transpose_kernel<<<dim3(32, 32, BS_), 256>>>(att);

    // GEMM1: V[m, n] = sum_k Wv[m,k] x[n,k] + bv[m]
    //   M=1024, N=32768  -> grid (256, 8)
    mm_tf32_kernel<<<dim3(ROWS / 128, D_ / 128, 1), 256>>>(
        (const float*)pWV, 1024, 0,
        (const float*)pXR, 1024, 0,
        (float*)pV, ROWS, 0,
        bv, 1);

    // GEMM2: out[b][m, n] = sum_k V[m, b*1024+k] attT[b][n, k]
    //   per batch M=N=1024 -> grid (8, 8, 32)
    mm_tf32_kernel<<<dim3(N_ / 128, D_ / 128, BS_), 256>>>(
        (const float*)pV, ROWS, 1024,
        (const float*)pAT, 1024, (size_t)N_ * N_,
        out, 1024, (size_t)D_ * N_,
        nullptr, 0);
}

// round 5
// speedup vs baseline: 2.8395x; 1.0866x over previous
#include <cuda_runtime.h>
#include <cstdint>

#define BS_   32
#define N_    1024
#define D_    1024
#define ROWS  (BS_ * N_)   // 32768

// ---- scratch (device globals; no allocation allowed) ----
__device__ float g_q[ROWS];
__device__ float g_k[ROWS];
__device__ float g_kmax[BS_];
__device__ float g_kmin[BS_];
__device__ float g_V[(size_t)D_ * ROWS];   // V[o][b*1024+n], ld=ROWS (tf32-rounded)

// ============================================================
// helpers
// ============================================================
__device__ __forceinline__ uint32_t smem_u32(const void* p) {
    uint32_t a;
    asm("{ .reg .u64 t; cvta.to.shared.u64 t, %1; cvt.u32.u64 %0, t; }" : "=r"(a) : "l"(p));
    return a;
}
__device__ __forceinline__ float f2tf32(float f) {
    uint32_t r;
    asm("cvt.rna.tf32.f32 %0, %1;" : "=r"(r) : "f"(f));
    return __uint_as_float(r);
}
#define CP_ASYNC16(smem, gptr) \
    asm volatile("cp.async.cg.shared.global [%0], [%1], 16;" :: "r"(smem), "l"(gptr))
#define CP_COMMIT() asm volatile("cp.async.commit_group;" ::: "memory")
#define CP_WAIT(n)  asm volatile("cp.async.wait_group %0;" :: "n"(n) : "memory")

__device__ __forceinline__ void mma_tf32(float c[4],
    uint32_t a0, uint32_t a1, uint32_t a2, uint32_t a3, uint32_t b0, uint32_t b1)
{
    asm volatile(
        "mma.sync.aligned.m16n8k8.row.col.f32.tf32.tf32.f32 "
        "{%0,%1,%2,%3}, {%4,%5,%6,%7}, {%8,%9}, {%0,%1,%2,%3};"
        : "+f"(c[0]), "+f"(c[1]), "+f"(c[2]), "+f"(c[3])
        : "r"(a0), "r"(a1), "r"(a2), "r"(a3), "r"(b0), "r"(b1));
}

// ============================================================
// Kernel 1: q/k dot products (one warp per row)
// ============================================================
__global__ __launch_bounds__(256) void qk_kernel(
    const float* __restrict__ x,
    const float* __restrict__ Wq, const float* __restrict__ Wk,
    const float* __restrict__ bq, const float* __restrict__ bk)
{
    int warp = threadIdx.x >> 5;
    int lane = threadIdx.x & 31;
    int row  = blockIdx.x * 8 + warp;
    const float* xr = x + (size_t)row * D_;

    float aq = 0.f, ak = 0.f;
#pragma unroll
    for (int i = 0; i < 8; i++) {
        int d = lane * 4 + i * 128;
        float4 xv = *(const float4*)(xr + d);
        float4 wq = *(const float4*)(Wq + d);
        float4 wk = *(const float4*)(Wk + d);
        aq += xv.x * wq.x + xv.y * wq.y + xv.z * wq.z + xv.w * wq.w;
        ak += xv.x * wk.x + xv.y * wk.y + xv.z * wk.z + xv.w * wk.w;
    }
#pragma unroll
    for (int o = 16; o; o >>= 1) {
        aq += __shfl_xor_sync(0xFFFFFFFFu, aq, o);
        ak += __shfl_xor_sync(0xFFFFFFFFu, ak, o);
    }
    if (lane == 0) {
        g_q[row] = aq + bq[0];
        g_k[row] = ak + bk[0];
    }
}

// ============================================================
// Kernel 2: per-batch max/min of k
// ============================================================
__global__ __launch_bounds__(256) void kminmax_kernel()
{
    __shared__ float smx[256], smn[256];
    int b = blockIdx.x;
    int tid = threadIdx.x;
    float4 kv = *(const float4*)&g_k[b * N_ + tid * 4];
    float mx = fmaxf(fmaxf(kv.x, kv.y), fmaxf(kv.z, kv.w));
    float mn = fminf(fminf(kv.x, kv.y), fminf(kv.z, kv.w));
    smx[tid] = mx; smn[tid] = mn;
    __syncthreads();
    for (int s = 128; s; s >>= 1) {
        if (tid < s) {
            smx[tid] = fmaxf(smx[tid], smx[tid + s]);
            smn[tid] = fminf(smn[tid], smn[tid + s]);
        }
        __syncthreads();
    }
    if (tid == 0) { g_kmax[b] = smx[0]; g_kmin[b] = smn[0]; }
}

// ============================================================
// Kernel 3: row softmax, warp-per-row (no smem, shuffle-only)
// ============================================================
__global__ __launch_bounds__(256) void softmax_kernel(float* __restrict__ att)
{
    int warp = threadIdx.x >> 5;
    int lane = threadIdx.x & 31;
    int row  = blockIdx.x * 8 + warp;
    int b    = row >> 10;

    float q  = g_q[row];
    float mx = (q >= 0.f) ? q * g_kmax[b] : q * g_kmin[b];
    const float* kr = g_k + b * N_;

    float e[32];
    float s = 0.f;
#pragma unroll
    for (int i = 0; i < 8; i++) {
        float4 kv = *(const float4*)(kr + i * 128 + lane * 4);
        e[i * 4 + 0] = __expf(fmaf(q, kv.x, -mx));
        e[i * 4 + 1] = __expf(fmaf(q, kv.y, -mx));
        e[i * 4 + 2] = __expf(fmaf(q, kv.z, -mx));
        e[i * 4 + 3] = __expf(fmaf(q, kv.w, -mx));
        s += e[i * 4] + e[i * 4 + 1] + e[i * 4 + 2] + e[i * 4 + 3];
    }
#pragma unroll
    for (int o = 16; o; o >>= 1) s += __shfl_xor_sync(0xFFFFFFFFu, s, o);
    float inv = 1.f / s;

    float* ar = att + (size_t)row * N_;
#pragma unroll
    for (int i = 0; i < 8; i++) {
        *(float4*)(ar + i * 128 + lane * 4) =
            make_float4(e[i * 4] * inv, e[i * 4 + 1] * inv,
                        e[i * 4 + 2] * inv, e[i * 4 + 3] * inv);
    }
}

// ============================================================
// tf32 mma.sync GEMM: C[m,n] = sum_k A[m,k]*B[n,k] (+bias[m])
//   BM=BN=128, BK=16, 256 thr, warp grid 2x4, warp tile 64x32
//   3-stage cp.async pipeline, 1 sync/iter, grid.x = m-tile.
//   BTRANS: B stored [K,N] n-major (staged transposed in smem)
//   RA/RB:  apply cvt.rna.tf32 to fragments in registers
// ============================================================
#define STAGES 3
#define NUM_IT 64                        // K=1024 / 16
#define A_PITCH 20
#define B0_PITCH 20
#define B1_PITCH 136
#define A_STG   (128 * A_PITCH)          // floats per A stage
#define B0_STG  (128 * B0_PITCH)
#define B1_STG  (16 * B1_PITCH)

template<int BTRANS, int RA, int RB>
__global__ __launch_bounds__(256) void mm_tf32_kernel(
    const float* __restrict__ A, int lda, size_t aOff,
    const float* __restrict__ B, int ldb, size_t bOff,
    float* __restrict__ C, int ldc, size_t cOff,
    const float* __restrict__ bias, int roundC)
{
    extern __shared__ float sm[];
    constexpr int B_STG = BTRANS ? B1_STG : B0_STG;
    float* As = sm;                          // [STAGES][128][A_PITCH]
    float* Bs = sm + STAGES * A_STG;         // [STAGES][..]

    const int tid = threadIdx.x;
    const int wid = tid >> 5, lane = tid & 31;
    const int tq = lane >> 2, tr = lane & 3;
    const int wm = (wid & 1) * 64, wn = (wid >> 1) * 32;
    const int m0 = blockIdx.x * 128, n0 = blockIdx.y * 128, b = blockIdx.z;

    const float* Ab = A + (size_t)b * aOff;
    const float* Bb = B + (size_t)b * bOff;
    float*       Cb = C + (size_t)b * cOff;

    // ---- staging addresses ----
    const int lrow = tid >> 2;            // 0..63
    const int lcol = (tid & 3) << 2;      // 0,4,8,12
    const float* Ag = Ab + (size_t)(m0 + lrow) * lda + lcol;
    const size_t a64 = (size_t)64 * lda;
    uint32_t sA0 = smem_u32(&As[lrow * A_PITCH + lcol]);
    uint32_t sA1 = smem_u32(&As[(lrow + 64) * A_PITCH + lcol]);

    // B staging (layout-dependent)
    const float* Bg0 = nullptr; size_t b64 = 0;
    uint32_t sB0 = 0, sB1 = 0;
    const float* Bg1 = nullptr;
    if (!BTRANS) {
        Bg0 = Bb + (size_t)(n0 + lrow) * ldb + lcol;
        b64 = (size_t)64 * ldb;
        sB0 = smem_u32(&Bs[lrow * B0_PITCH + lcol]);
        sB1 = smem_u32(&Bs[(lrow + 64) * B0_PITCH + lcol]);
    } else {
        int kk = tid >> 4;                // 0..15
        int nc = (tid & 15) << 3;         // 0,8,..,120 floats
        Bg1 = Bb + (size_t)kk * ldb + n0 + nc;
        sB0 = smem_u32(&Bs[kk * B1_PITCH + nc]);
    }

    const uint32_t aStgB = A_STG * 4;     // stage strides in bytes
    const uint32_t bStgB = B_STG * 4;

    float c[4][4][4] = {};

    // ---- prologue: prefetch stages 0,1 ----
#pragma unroll
    for (int p = 0; p < 2; p++) {
        int koff = p * 16;
        CP_ASYNC16(sA0 + p * aStgB, Ag + koff);
        CP_ASYNC16(sA1 + p * aStgB, Ag + koff + a64);
        if (!BTRANS) {
            CP_ASYNC16(sB0 + p * bStgB, Bg0 + koff);
            CP_ASYNC16(sB1 + p * bStgB, Bg0 + koff + b64);
        } else {
            const float* src = Bg1 + (size_t)koff * ldb;
            CP_ASYNC16(sB0 + p * bStgB, src);
            CP_ASYNC16(sB0 + p * bStgB + 16, src + 4);
        }
        CP_COMMIT();
    }

#pragma unroll 1
    for (int it = 0; it < NUM_IT; ++it) {
        CP_WAIT(1);
        __syncthreads();

        // prefetch stage it+2 into buffer (it+2)%3
        if (it + 2 < NUM_IT) {
            int ps = (it + 2) % STAGES;
            int koff = (it + 2) * 16;
            CP_ASYNC16(sA0 + ps * aStgB, Ag + koff);
            CP_ASYNC16(sA1 + ps * aStgB, Ag + koff + a64);
            if (!BTRANS) {
                CP_ASYNC16(sB0 + ps * bStgB, Bg0 + koff);
                CP_ASYNC16(sB1 + ps * bStgB, Bg0 + koff + b64);
            } else {
                const float* src = Bg1 + (size_t)koff * ldb;
                CP_ASYNC16(sB0 + ps * bStgB, src);
                CP_ASYNC16(sB0 + ps * bStgB + 16, src + 4);
            }
        }
        CP_COMMIT();

        // ---- compute on buffer it%3 ----
        const float* Ast = As + (it % STAGES) * A_STG;
        const float* Bst = Bs + (it % STAGES) * B_STG;

#pragma unroll
        for (int ks = 0; ks < 16; ks += 8) {
            uint32_t a[4][4], bb[4][2];
#pragma unroll
            for (int i = 0; i < 4; i++) {
                float v0 = Ast[(wm + i * 16 + tq) * A_PITCH + ks + tr];
                float v1 = Ast[(wm + i * 16 + tq + 8) * A_PITCH + ks + tr];
                float v2 = Ast[(wm + i * 16 + tq) * A_PITCH + ks + tr + 4];
                float v3 = Ast[(wm + i * 16 + tq + 8) * A_PITCH + ks + tr + 4];
                if (RA) { v0 = f2tf32(v0); v1 = f2tf32(v1); v2 = f2tf32(v2); v3 = f2tf32(v3); }
                a[i][0] = __float_as_uint(v0); a[i][1] = __float_as_uint(v1);
                a[i][2] = __float_as_uint(v2); a[i][3] = __float_as_uint(v3);
            }
#pragma unroll
            for (int j = 0; j < 4; j++) {
                float v0, v1;
                if (!BTRANS) {
                    v0 = Bst[(wn + j * 8 + tq) * B0_PITCH + ks + tr];
                    v1 = Bst[(wn + j * 8 + tq) * B0_PITCH + ks + tr + 4];
                } else {
                    v0 = Bst[(ks + tr) * B1_PITCH + wn + j * 8 + tq];
                    v1 = Bst[(ks + tr + 4) * B1_PITCH + wn + j * 8 + tq];
                }
                if (RB) { v0 = f2tf32(v0); v1 = f2tf32(v1); }
                bb[j][0] = __float_as_uint(v0); bb[j][1] = __float_as_uint(v1);
            }
#pragma unroll
            for (int i = 0; i < 4; i++)
#pragma unroll
                for (int j = 0; j < 4; j++)
                    mma_tf32(c[i][j], a[i][0], a[i][1], a[i][2], a[i][3],
                             bb[j][0], bb[j][1]);
        }
    }

    // ---- epilogue ----
#pragma unroll
    for (int i = 0; i < 4; i++) {
        int r0 = m0 + wm + i * 16 + tq;
        int r1 = r0 + 8;
        float bi0 = bias ? bias[r0] : 0.f;
        float bi1 = bias ? bias[r1] : 0.f;
#pragma unroll
        for (int j = 0; j < 4; j++) {
            int col = n0 + wn + j * 8 + tr * 2;
            float2 v0 = make_float2(c[i][j][0] + bi0, c[i][j][1] + bi0);
            float2 v1 = make_float2(c[i][j][2] + bi1, c[i][j][3] + bi1);
            if (roundC) {
                v0.x = f2tf32(v0.x); v0.y = f2tf32(v0.y);
                v1.x = f2tf32(v1.x); v1.y = f2tf32(v1.y);
            }
            *(float2*)(Cb + (size_t)r0 * ldc + col) = v0;
            *(float2*)(Cb + (size_t)r1 * ldc + col) = v1;
        }
    }
}

// ============================================================
extern "C" void kernel_launch(void* const* d_in, const int* in_sizes, int n_in,
                              void* d_out, int out_size)
{
    const float* x  = (const float*)d_in[0];
    const float* Wq = (const float*)d_in[1];
    const float* bq = (const float*)d_in[2];
    const float* Wk = (const float*)d_in[3];
    const float* bk = (const float*)d_in[4];
    const float* Wv = (const float*)d_in[5];
    const float* bv = (const float*)d_in[6];

    float* out = (float*)d_out;                   // (bs, d, n) raw layout
    float* att = out + (size_t)BS_ * N_ * D_;     // (bs, n, n)

    void* pV;
    cudaGetSymbolAddress(&pV, g_V);

    const int smem0 = STAGES * (A_STG + B0_STG) * 4;   // 61440 B
    const int smem1 = STAGES * (A_STG + B1_STG) * 4;   // 56832 B
    static bool attr_done = false;
    if (!attr_done) {
        cudaFuncSetAttribute(mm_tf32_kernel<0, 1, 1>,
                             cudaFuncAttributeMaxDynamicSharedMemorySize, smem0);
        cudaFuncSetAttribute(mm_tf32_kernel<1, 0, 1>,
                             cudaFuncAttributeMaxDynamicSharedMemorySize, smem1);
        attr_done = true;
    }

    qk_kernel<<<ROWS / 8, 256>>>(x, Wq, Wk, bq, bk);
    kminmax_kernel<<<BS_, 256>>>();
    softmax_kernel<<<ROWS / 8, 256>>>(att);

    // GEMM1: V[m,n] = sum_k Wv[m,k] x[n,k] + bv[m]
    //   grid.x = m-tiles (8), grid.y = n-tiles (256)
    mm_tf32_kernel<0, 1, 1><<<dim3(D_ / 128, ROWS / 128, 1), 256, smem0>>>(
        Wv, 1024, 0,
        x, 1024, 0,
        (float*)pV, ROWS, 0,
        bv, 1);

    // GEMM2: out[b][m,n] = sum_k V[m, b*1024+k] att[b][k,n]   (B n-major)
    mm_tf32_kernel<1, 0, 1><<<dim3(D_ / 128, N_ / 128, BS_), 256, smem1>>>(
        (const float*)pV, ROWS, 1024,
        att, 1024, (size_t)N_ * N_,
        out, 1024, (size_t)D_ * N_,
        nullptr, 0);
}

// round 6
// speedup vs baseline: 2.8410x; 1.0005x over previous
#include <cuda_runtime.h>
#include <cstdint>

#define BS_   32
#define N_    1024
#define D_    1024
#define ROWS  (BS_ * N_)   // 32768

// ---- scratch (device globals; no allocation allowed) ----
__device__ float g_q[ROWS];
__device__ float g_k[ROWS];
__device__ float g_kmax[BS_];
__device__ float g_kmin[BS_];
__device__ float g_V[(size_t)D_ * ROWS];   // V[o][b*1024+n], ld=ROWS (tf32-rounded)

// ============================================================
// helpers
// ============================================================
__device__ __forceinline__ uint32_t smem_u32(const void* p) {
    uint32_t a;
    asm("{ .reg .u64 t; cvta.to.shared.u64 t, %1; cvt.u32.u64 %0, t; }" : "=r"(a) : "l"(p));
    return a;
}
__device__ __forceinline__ float f2tf32(float f) {
    uint32_t r;
    asm("cvt.rna.tf32.f32 %0, %1;" : "=r"(r) : "f"(f));
    return __uint_as_float(r);
}
#define CP_ASYNC16(smem, gptr) \
    asm volatile("cp.async.cg.shared.global [%0], [%1], 16;" :: "r"(smem), "l"(gptr))
#define CP_COMMIT() asm volatile("cp.async.commit_group;" ::: "memory")
#define CP_WAIT(n)  asm volatile("cp.async.wait_group %0;" :: "n"(n) : "memory")

__device__ __forceinline__ void mma_tf32(float c[4],
    uint32_t a0, uint32_t a1, uint32_t a2, uint32_t a3, uint32_t b0, uint32_t b1)
{
    asm volatile(
        "mma.sync.aligned.m16n8k8.row.col.f32.tf32.tf32.f32 "
        "{%0,%1,%2,%3}, {%4,%5,%6,%7}, {%8,%9}, {%0,%1,%2,%3};"
        : "+f"(c[0]), "+f"(c[1]), "+f"(c[2]), "+f"(c[3])
        : "r"(a0), "r"(a1), "r"(a2), "r"(a3), "r"(b0), "r"(b1));
}

// ============================================================
// Kernel 1: q/k dot products (one warp per row)
// ============================================================
__global__ __launch_bounds__(256) void qk_kernel(
    const float* __restrict__ x,
    const float* __restrict__ Wq, const float* __restrict__ Wk,
    const float* __restrict__ bq, const float* __restrict__ bk)
{
    int warp = threadIdx.x >> 5;
    int lane = threadIdx.x & 31;
    int row  = blockIdx.x * 8 + warp;
    const float* xr = x + (size_t)row * D_;

    float aq = 0.f, ak = 0.f;
#pragma unroll
    for (int i = 0; i < 8; i++) {
        int d = lane * 4 + i * 128;
        float4 xv = *(const float4*)(xr + d);
        float4 wq = *(const float4*)(Wq + d);
        float4 wk = *(const float4*)(Wk + d);
        aq += xv.x * wq.x + xv.y * wq.y + xv.z * wq.z + xv.w * wq.w;
        ak += xv.x * wk.x + xv.y * wk.y + xv.z * wk.z + xv.w * wk.w;
    }
#pragma unroll
    for (int o = 16; o; o >>= 1) {
        aq += __shfl_xor_sync(0xFFFFFFFFu, aq, o);
        ak += __shfl_xor_sync(0xFFFFFFFFu, ak, o);
    }
    if (lane == 0) {
        g_q[row] = aq + bq[0];
        g_k[row] = ak + bk[0];
    }
}

// ============================================================
// Kernel 2: per-batch max/min of k
// ============================================================
__global__ __launch_bounds__(256) void kminmax_kernel()
{
    __shared__ float smx[256], smn[256];
    int b = blockIdx.x;
    int tid = threadIdx.x;
    float4 kv = *(const float4*)&g_k[b * N_ + tid * 4];
    float mx = fmaxf(fmaxf(kv.x, kv.y), fmaxf(kv.z, kv.w));
    float mn = fminf(fminf(kv.x, kv.y), fminf(kv.z, kv.w));
    smx[tid] = mx; smn[tid] = mn;
    __syncthreads();
    for (int s = 128; s; s >>= 1) {
        if (tid < s) {
            smx[tid] = fmaxf(smx[tid], smx[tid + s]);
            smn[tid] = fminf(smn[tid], smn[tid + s]);
        }
        __syncthreads();
    }
    if (tid == 0) { g_kmax[b] = smx[0]; g_kmin[b] = smn[0]; }
}

// ============================================================
// Kernel 3: row softmax, warp-per-row (no smem, shuffle-only)
// ============================================================
__global__ __launch_bounds__(256) void softmax_kernel(float* __restrict__ att)
{
    int warp = threadIdx.x >> 5;
    int lane = threadIdx.x & 31;
    int row  = blockIdx.x * 8 + warp;
    int b    = row >> 10;

    float q  = g_q[row];
    float mx = (q >= 0.f) ? q * g_kmax[b] : q * g_kmin[b];
    const float* kr = g_k + b * N_;

    float e[32];
    float s = 0.f;
#pragma unroll
    for (int i = 0; i < 8; i++) {
        float4 kv = *(const float4*)(kr + i * 128 + lane * 4);
        e[i * 4 + 0] = __expf(fmaf(q, kv.x, -mx));
        e[i * 4 + 1] = __expf(fmaf(q, kv.y, -mx));
        e[i * 4 + 2] = __expf(fmaf(q, kv.z, -mx));
        e[i * 4 + 3] = __expf(fmaf(q, kv.w, -mx));
        s += e[i * 4] + e[i * 4 + 1] + e[i * 4 + 2] + e[i * 4 + 3];
    }
#pragma unroll
    for (int o = 16; o; o >>= 1) s += __shfl_xor_sync(0xFFFFFFFFu, s, o);
    float inv = 1.f / s;

    float* ar = att + (size_t)row * N_;
#pragma unroll
    for (int i = 0; i < 8; i++) {
        *(float4*)(ar + i * 128 + lane * 4) =
            make_float4(e[i * 4] * inv, e[i * 4 + 1] * inv,
                        e[i * 4 + 2] * inv, e[i * 4 + 3] * inv);
    }
}

// ============================================================
// tf32 mma.sync GEMM: C[m,n] = sum_k A[m,k]*B[n,k] (+bias[m])
//   BM=BN=128, BK=16, 256 thr, warp grid 2x4, warp tile 64x32
//   3-stage cp.async pipeline, 1 sync/iter, grid.x = m-tile.
//   BTRANS: B stored [K,N] n-major (staged transposed in smem)
//   RA/RB:  apply cvt.rna.tf32 to fragments in registers
// ============================================================
#define STAGES 3
#define NUM_IT 64                        // K=1024 / 16
#define A_PITCH 20
#define B0_PITCH 20
#define B1_PITCH 136
#define A_STG   (128 * A_PITCH)          // floats per A stage
#define B0_STG  (128 * B0_PITCH)
#define B1_STG  (16 * B1_PITCH)

template<int BTRANS, int RA, int RB>
__global__ __launch_bounds__(256) void mm_tf32_kernel(
    const float* __restrict__ A, int lda, size_t aOff,
    const float* __restrict__ B, int ldb, size_t bOff,
    float* __restrict__ C, int ldc, size_t cOff,
    const float* __restrict__ bias, int roundC)
{
    extern __shared__ float sm[];
    constexpr int B_STG = BTRANS ? B1_STG : B0_STG;
    float* As = sm;                          // [STAGES][128][A_PITCH]
    float* Bs = sm + STAGES * A_STG;         // [STAGES][..]

    const int tid = threadIdx.x;
    const int wid = tid >> 5, lane = tid & 31;
    const int tq = lane >> 2, tr = lane & 3;
    const int wm = (wid & 1) * 64, wn = (wid >> 1) * 32;
    const int m0 = blockIdx.x * 128, n0 = blockIdx.y * 128, b = blockIdx.z;

    const float* Ab = A + (size_t)b * aOff;
    const float* Bb = B + (size_t)b * bOff;
    float*       Cb = C + (size_t)b * cOff;

    // ---- staging addresses ----
    const int lrow = tid >> 2;            // 0..63
    const int lcol = (tid & 3) << 2;      // 0,4,8,12
    const float* Ag = Ab + (size_t)(m0 + lrow) * lda + lcol;
    const size_t a64 = (size_t)64 * lda;
    uint32_t sA0 = smem_u32(&As[lrow * A_PITCH + lcol]);
    uint32_t sA1 = smem_u32(&As[(lrow + 64) * A_PITCH + lcol]);

    // B staging (layout-dependent)
    const float* Bg0 = nullptr; size_t b64 = 0;
    uint32_t sB0 = 0, sB1 = 0;
    const float* Bg1 = nullptr;
    if (!BTRANS) {
        Bg0 = Bb + (size_t)(n0 + lrow) * ldb + lcol;
        b64 = (size_t)64 * ldb;
        sB0 = smem_u32(&Bs[lrow * B0_PITCH + lcol]);
        sB1 = smem_u32(&Bs[(lrow + 64) * B0_PITCH + lcol]);
    } else {
        int kk = tid >> 4;                // 0..15
        int nc = (tid & 15) << 3;         // 0,8,..,120 floats
        Bg1 = Bb + (size_t)kk * ldb + n0 + nc;
        sB0 = smem_u32(&Bs[kk * B1_PITCH + nc]);
    }

    const uint32_t aStgB = A_STG * 4;     // stage strides in bytes
    const uint32_t bStgB = B_STG * 4;

    float c[4][4][4] = {};

    // ---- prologue: prefetch stages 0,1 ----
#pragma unroll
    for (int p = 0; p < 2; p++) {
        int koff = p * 16;
        CP_ASYNC16(sA0 + p * aStgB, Ag + koff);
        CP_ASYNC16(sA1 + p * aStgB, Ag + koff + a64);
        if (!BTRANS) {
            CP_ASYNC16(sB0 + p * bStgB, Bg0 + koff);
            CP_ASYNC16(sB1 + p * bStgB, Bg0 + koff + b64);
        } else {
            const float* src = Bg1 + (size_t)koff * ldb;
            CP_ASYNC16(sB0 + p * bStgB, src);
            CP_ASYNC16(sB0 + p * bStgB + 16, src + 4);
        }
        CP_COMMIT();
    }

#pragma unroll 1
    for (int it = 0; it < NUM_IT; ++it) {
        CP_WAIT(1);
        __syncthreads();

        // prefetch stage it+2 into buffer (it+2)%3
        if (it + 2 < NUM_IT) {
            int ps = (it + 2) % STAGES;
            int koff = (it + 2) * 16;
            CP_ASYNC16(sA0 + ps * aStgB, Ag + koff);
            CP_ASYNC16(sA1 + ps * aStgB, Ag + koff + a64);
            if (!BTRANS) {
                CP_ASYNC16(sB0 + ps * bStgB, Bg0 + koff);
                CP_ASYNC16(sB1 + ps * bStgB, Bg0 + koff + b64);
            } else {
                const float* src = Bg1 + (size_t)koff * ldb;
                CP_ASYNC16(sB0 + ps * bStgB, src);
                CP_ASYNC16(sB0 + ps * bStgB + 16, src + 4);
            }
        }
        CP_COMMIT();

        // ---- compute on buffer it%3 ----
        const float* Ast = As + (it % STAGES) * A_STG;
        const float* Bst = Bs + (it % STAGES) * B_STG;

#pragma unroll
        for (int ks = 0; ks < 16; ks += 8) {
            uint32_t a[4][4], bb[4][2];
#pragma unroll
            for (int i = 0; i < 4; i++) {
                float v0 = Ast[(wm + i * 16 + tq) * A_PITCH + ks + tr];
                float v1 = Ast[(wm + i * 16 + tq + 8) * A_PITCH + ks + tr];
                float v2 = Ast[(wm + i * 16 + tq) * A_PITCH + ks + tr + 4];
                float v3 = Ast[(wm + i * 16 + tq + 8) * A_PITCH + ks + tr + 4];
                if (RA) { v0 = f2tf32(v0); v1 = f2tf32(v1); v2 = f2tf32(v2); v3 = f2tf32(v3); }
                a[i][0] = __float_as_uint(v0); a[i][1] = __float_as_uint(v1);
                a[i][2] = __float_as_uint(v2); a[i][3] = __float_as_uint(v3);
            }
#pragma unroll
            for (int j = 0; j < 4; j++) {
                float v0, v1;
                if (!BTRANS) {
                    v0 = Bst[(wn + j * 8 + tq) * B0_PITCH + ks + tr];
                    v1 = Bst[(wn + j * 8 + tq) * B0_PITCH + ks + tr + 4];
                } else {
                    v0 = Bst[(ks + tr) * B1_PITCH + wn + j * 8 + tq];
                    v1 = Bst[(ks + tr + 4) * B1_PITCH + wn + j * 8 + tq];
                }
                if (RB) { v0 = f2tf32(v0); v1 = f2tf32(v1); }
                bb[j][0] = __float_as_uint(v0); bb[j][1] = __float_as_uint(v1);
            }
#pragma unroll
            for (int i = 0; i < 4; i++)
#pragma unroll
                for (int j = 0; j < 4; j++)
                    mma_tf32(c[i][j], a[i][0], a[i][1], a[i][2], a[i][3],
                             bb[j][0], bb[j][1]);
        }
    }

    // ---- epilogue ----
#pragma unroll
    for (int i = 0; i < 4; i++) {
        int r0 = m0 + wm + i * 16 + tq;
        int r1 = r0 + 8;
        float bi0 = bias ? bias[r0] : 0.f;
        float bi1 = bias ? bias[r1] : 0.f;
#pragma unroll
        for (int j = 0; j < 4; j++) {
            int col = n0 + wn + j * 8 + tr * 2;
            float2 v0 = make_float2(c[i][j][0] + bi0, c[i][j][1] + bi0);
            float2 v1 = make_float2(c[i][j][2] + bi1, c[i][j][3] + bi1);
            if (roundC) {
                v0.x = f2tf32(v0.x); v0.y = f2tf32(v0.y);
                v1.x = f2tf32(v1.x); v1.y = f2tf32(v1.y);
            }
            *(float2*)(Cb + (size_t)r0 * ldc + col) = v0;
            *(float2*)(Cb + (size_t)r1 * ldc + col) = v1;
        }
    }
}

// ============================================================
extern "C" void kernel_launch(void* const* d_in, const int* in_sizes, int n_in,
                              void* d_out, int out_size)
{
    const float* x  = (const float*)d_in[0];
    const float* Wq = (const float*)d_in[1];
    const float* bq = (const float*)d_in[2];
    const float* Wk = (const float*)d_in[3];
    const float* bk = (const float*)d_in[4];
    const float* Wv = (const float*)d_in[5];
    const float* bv = (const float*)d_in[6];

    float* out = (float*)d_out;                   // (bs, d, n) raw layout
    float* att = out + (size_t)BS_ * N_ * D_;     // (bs, n, n)

    void* pV;
    cudaGetSymbolAddress(&pV, g_V);

    const int smem0 = STAGES * (A_STG + B0_STG) * 4;   // 61440 B
    const int smem1 = STAGES * (A_STG + B1_STG) * 4;   // 56832 B
    static bool attr_done = false;
    if (!attr_done) {
        cudaFuncSetAttribute(mm_tf32_kernel<0, 1, 1>,
                             cudaFuncAttributeMaxDynamicSharedMemorySize, smem0);
        cudaFuncSetAttribute(mm_tf32_kernel<1, 0, 1>,
                             cudaFuncAttributeMaxDynamicSharedMemorySize, smem1);
        attr_done = true;
    }

    qk_kernel<<<ROWS / 8, 256>>>(x, Wq, Wk, bq, bk);
    kminmax_kernel<<<BS_, 256>>>();
    softmax_kernel<<<ROWS / 8, 256>>>(att);

    // GEMM1: V[m,n] = sum_k Wv[m,k] x[n,k] + bv[m]
    //   grid.x = m-tiles (8), grid.y = n-tiles (256)
    mm_tf32_kernel<0, 1, 1><<<dim3(D_ / 128, ROWS / 128, 1), 256, smem0>>>(
        Wv, 1024, 0,
        x, 1024, 0,
        (float*)pV, ROWS, 0,
        bv, 1);

    // GEMM2: out[b][m,n] = sum_k V[m, b*1024+k] att[b][k,n]   (B n-major)
    mm_tf32_kernel<1, 0, 1><<<dim3(D_ / 128, N_ / 128, BS_), 256, smem1>>>(
        (const float*)pV, ROWS, 1024,
        att, 1024, (size_t)N_ * N_,
        out, 1024, (size_t)D_ * N_,
        nullptr, 0);
}

// round 7
// speedup vs baseline: 2.8433x; 1.0008x over previous
#include <cuda_runtime.h>
#include <cstdint>

#define BS_   32
#define N_    1024
#define D_    1024
#define ROWS  (BS_ * N_)   // 32768

// ---- scratch (device globals; no allocation allowed) ----
__device__ float g_q[ROWS];
__device__ float g_k[ROWS];
__device__ float g_kmax[BS_];
__device__ float g_kmin[BS_];
__device__ float g_V[(size_t)D_ * ROWS];   // V[o][b*1024+n], ld=ROWS (tf32-rounded)

// ============================================================
// helpers
// ============================================================
__device__ __forceinline__ uint32_t smem_u32(const void* p) {
    uint32_t a;
    asm("{ .reg .u64 t; cvta.to.shared.u64 t, %1; cvt.u32.u64 %0, t; }" : "=r"(a) : "l"(p));
    return a;
}
__device__ __forceinline__ float f2tf32(float f) {
    uint32_t r;
    asm("cvt.rna.tf32.f32 %0, %1;" : "=r"(r) : "f"(f));
    return __uint_as_float(r);
}
#define CP_ASYNC16(smem, gptr) \
    asm volatile("cp.async.cg.shared.global [%0], [%1], 16;" :: "r"(smem), "l"(gptr))
#define CP_COMMIT() asm volatile("cp.async.commit_group;" ::: "memory")
#define CP_WAIT(n)  asm volatile("cp.async.wait_group %0;" :: "n"(n) : "memory")

__device__ __forceinline__ void mma_tf32(float c[4],
    uint32_t a0, uint32_t a1, uint32_t a2, uint32_t a3, uint32_t b0, uint32_t b1)
{
    asm volatile(
        "mma.sync.aligned.m16n8k8.row.col.f32.tf32.tf32.f32 "
        "{%0,%1,%2,%3}, {%4,%5,%6,%7}, {%8,%9}, {%0,%1,%2,%3};"
        : "+f"(c[0]), "+f"(c[1]), "+f"(c[2]), "+f"(c[3])
        : "r"(a0), "r"(a1), "r"(a2), "r"(a3), "r"(b0), "r"(b1));
}

// ============================================================
// Kernel 1: q/k dot products (one warp per row)
// ============================================================
__global__ __launch_bounds__(256) void qk_kernel(
    const float* __restrict__ x,
    const float* __restrict__ Wq, const float* __restrict__ Wk,
    const float* __restrict__ bq, const float* __restrict__ bk)
{
    int warp = threadIdx.x >> 5;
    int lane = threadIdx.x & 31;
    int row  = blockIdx.x * 8 + warp;
    const float* xr = x + (size_t)row * D_;

    float aq = 0.f, ak = 0.f;
#pragma unroll
    for (int i = 0; i < 8; i++) {
        int d = lane * 4 + i * 128;
        float4 xv = *(const float4*)(xr + d);
        float4 wq = *(const float4*)(Wq + d);
        float4 wk = *(const float4*)(Wk + d);
        aq += xv.x * wq.x + xv.y * wq.y + xv.z * wq.z + xv.w * wq.w;
        ak += xv.x * wk.x + xv.y * wk.y + xv.z * wk.z + xv.w * wk.w;
    }
#pragma unroll
    for (int o = 16; o; o >>= 1) {
        aq += __shfl_xor_sync(0xFFFFFFFFu, aq, o);
        ak += __shfl_xor_sync(0xFFFFFFFFu, ak, o);
    }
    if (lane == 0) {
        g_q[row] = aq + bq[0];
        g_k[row] = ak + bk[0];
    }
}

// ============================================================
// Kernel 2: per-batch max/min of k
// ============================================================
__global__ __launch_bounds__(256) void kminmax_kernel()
{
    __shared__ float smx[256], smn[256];
    int b = blockIdx.x;
    int tid = threadIdx.x;
    float4 kv = *(const float4*)&g_k[b * N_ + tid * 4];
    float mx = fmaxf(fmaxf(kv.x, kv.y), fmaxf(kv.z, kv.w));
    float mn = fminf(fminf(kv.x, kv.y), fminf(kv.z, kv.w));
    smx[tid] = mx; smn[tid] = mn;
    __syncthreads();
    for (int s = 128; s; s >>= 1) {
        if (tid < s) {
            smx[tid] = fmaxf(smx[tid], smx[tid + s]);
            smn[tid] = fminf(smn[tid], smn[tid + s]);
        }
        __syncthreads();
    }
    if (tid == 0) { g_kmax[b] = smx[0]; g_kmin[b] = smn[0]; }
}

// ============================================================
// Kernel 3: row softmax, warp-per-row (no smem, shuffle-only)
// ============================================================
__global__ __launch_bounds__(256) void softmax_kernel(float* __restrict__ att)
{
    int warp = threadIdx.x >> 5;
    int lane = threadIdx.x & 31;
    int row  = blockIdx.x * 8 + warp;
    int b    = row >> 10;

    float q  = g_q[row];
    float mx = (q >= 0.f) ? q * g_kmax[b] : q * g_kmin[b];
    const float* kr = g_k + b * N_;

    float e[32];
    float s = 0.f;
#pragma unroll
    for (int i = 0; i < 8; i++) {
        float4 kv = *(const float4*)(kr + i * 128 + lane * 4);
        e[i * 4 + 0] = __expf(fmaf(q, kv.x, -mx));
        e[i * 4 + 1] = __expf(fmaf(q, kv.y, -mx));
        e[i * 4 + 2] = __expf(fmaf(q, kv.z, -mx));
        e[i * 4 + 3] = __expf(fmaf(q, kv.w, -mx));
        s += e[i * 4] + e[i * 4 + 1] + e[i * 4 + 2] + e[i * 4 + 3];
    }
#pragma unroll
    for (int o = 16; o; o >>= 1) s += __shfl_xor_sync(0xFFFFFFFFu, s, o);
    float inv = 1.f / s;

    float* ar = att + (size_t)row * N_;
#pragma unroll
    for (int i = 0; i < 8; i++) {
        *(float4*)(ar + i * 128 + lane * 4) =
            make_float4(e[i * 4] * inv, e[i * 4 + 1] * inv,
                        e[i * 4 + 2] * inv, e[i * 4 + 3] * inv);
    }
}

// ============================================================
// tf32 mma.sync GEMM: C[m,n] = sum_k A[m,k]*B[n,k] (+bias[m])
//   BM=BN=128, BK=16, 256 thr, warp grid 2x4, warp tile 64x32
//   3-stage cp.async pipeline, 1 sync/iter, grid.x = m-tile.
//   BTRANS: B stored [K,N] n-major (staged transposed in smem)
//   RA/RB:  apply cvt.rna.tf32 to fragments in registers
// ============================================================
#define STAGES 3
#define NUM_IT 64                        // K=1024 / 16
#define A_PITCH 20
#define B0_PITCH 20
#define B1_PITCH 136
#define A_STG   (128 * A_PITCH)          // floats per A stage
#define B0_STG  (128 * B0_PITCH)
#define B1_STG  (16 * B1_PITCH)

template<int BTRANS, int RA, int RB>
__global__ __launch_bounds__(256) void mm_tf32_kernel(
    const float* __restrict__ A, int lda, size_t aOff,
    const float* __restrict__ B, int ldb, size_t bOff,
    float* __restrict__ C, int ldc, size_t cOff,
    const float* __restrict__ bias, int roundC)
{
    extern __shared__ float sm[];
    constexpr int B_STG = BTRANS ? B1_STG : B0_STG;
    float* As = sm;                          // [STAGES][128][A_PITCH]
    float* Bs = sm + STAGES * A_STG;         // [STAGES][..]

    const int tid = threadIdx.x;
    const int wid = tid >> 5, lane = tid & 31;
    const int tq = lane >> 2, tr = lane & 3;
    const int wm = (wid & 1) * 64, wn = (wid >> 1) * 32;
    const int m0 = blockIdx.x * 128, n0 = blockIdx.y * 128, b = blockIdx.z;

    const float* Ab = A + (size_t)b * aOff;
    const float* Bb = B + (size_t)b * bOff;
    float*       Cb = C + (size_t)b * cOff;

    // ---- staging addresses ----
    const int lrow = tid >> 2;            // 0..63
    const int lcol = (tid & 3) << 2;      // 0,4,8,12
    const float* Ag = Ab + (size_t)(m0 + lrow) * lda + lcol;
    const size_t a64 = (size_t)64 * lda;
    uint32_t sA0 = smem_u32(&As[lrow * A_PITCH + lcol]);
    uint32_t sA1 = smem_u32(&As[(lrow + 64) * A_PITCH + lcol]);

    // B staging (layout-dependent)
    const float* Bg0 = nullptr; size_t b64 = 0;
    uint32_t sB0 = 0, sB1 = 0;
    const float* Bg1 = nullptr;
    if (!BTRANS) {
        Bg0 = Bb + (size_t)(n0 + lrow) * ldb + lcol;
        b64 = (size_t)64 * ldb;
        sB0 = smem_u32(&Bs[lrow * B0_PITCH + lcol]);
        sB1 = smem_u32(&Bs[(lrow + 64) * B0_PITCH + lcol]);
    } else {
        int kk = tid >> 4;                // 0..15
        int nc = (tid & 15) << 3;         // 0,8,..,120 floats
        Bg1 = Bb + (size_t)kk * ldb + n0 + nc;
        sB0 = smem_u32(&Bs[kk * B1_PITCH + nc]);
    }

    const uint32_t aStgB = A_STG * 4;     // stage strides in bytes
    const uint32_t bStgB = B_STG * 4;

    float c[4][4][4] = {};

    // ---- prologue: prefetch stages 0,1 ----
#pragma unroll
    for (int p = 0; p < 2; p++) {
        int koff = p * 16;
        CP_ASYNC16(sA0 + p * aStgB, Ag + koff);
        CP_ASYNC16(sA1 + p * aStgB, Ag + koff + a64);
        if (!BTRANS) {
            CP_ASYNC16(sB0 + p * bStgB, Bg0 + koff);
            CP_ASYNC16(sB1 + p * bStgB, Bg0 + koff + b64);
        } else {
            const float* src = Bg1 + (size_t)koff * ldb;
            CP_ASYNC16(sB0 + p * bStgB, src);
            CP_ASYNC16(sB0 + p * bStgB + 16, src + 4);
        }
        CP_COMMIT();
    }

#pragma unroll 1
    for (int it = 0; it < NUM_IT; ++it) {
        CP_WAIT(1);
        __syncthreads();

        // prefetch stage it+2 into buffer (it+2)%3
        if (it + 2 < NUM_IT) {
            int ps = (it + 2) % STAGES;
            int koff = (it + 2) * 16;
            CP_ASYNC16(sA0 + ps * aStgB, Ag + koff);
            CP_ASYNC16(sA1 + ps * aStgB, Ag + koff + a64);
            if (!BTRANS) {
                CP_ASYNC16(sB0 + ps * bStgB, Bg0 + koff);
                CP_ASYNC16(sB1 + ps * bStgB, Bg0 + koff + b64);
            } else {
                const float* src = Bg1 + (size_t)koff * ldb;
                CP_ASYNC16(sB0 + ps * bStgB, src);
                CP_ASYNC16(sB0 + ps * bStgB + 16, src + 4);
            }
        }
        CP_COMMIT();

        // ---- compute on buffer it%3 ----
        const float* Ast = As + (it % STAGES) * A_STG;
        const float* Bst = Bs + (it % STAGES) * B_STG;

#pragma unroll
        for (int ks = 0; ks < 16; ks += 8) {
            uint32_t a[4][4], bb[4][2];
#pragma unroll
            for (int i = 0; i < 4; i++) {
                float v0 = Ast[(wm + i * 16 + tq) * A_PITCH + ks + tr];
                float v1 = Ast[(wm + i * 16 + tq + 8) * A_PITCH + ks + tr];
                float v2 = Ast[(wm + i * 16 + tq) * A_PITCH + ks + tr + 4];
                float v3 = Ast[(wm + i * 16 + tq + 8) * A_PITCH + ks + tr + 4];
                if (RA) { v0 = f2tf32(v0); v1 = f2tf32(v1); v2 = f2tf32(v2); v3 = f2tf32(v3); }
                a[i][0] = __float_as_uint(v0); a[i][1] = __float_as_uint(v1);
                a[i][2] = __float_as_uint(v2); a[i][3] = __float_as_uint(v3);
            }
#pragma unroll
            for (int j = 0; j < 4; j++) {
                float v0, v1;
                if (!BTRANS) {
                    v0 = Bst[(wn + j * 8 + tq) * B0_PITCH + ks + tr];
                    v1 = Bst[(wn + j * 8 + tq) * B0_PITCH + ks + tr + 4];
                } else {
                    v0 = Bst[(ks + tr) * B1_PITCH + wn + j * 8 + tq];
                    v1 = Bst[(ks + tr + 4) * B1_PITCH + wn + j * 8 + tq];
                }
                if (RB) { v0 = f2tf32(v0); v1 = f2tf32(v1); }
                bb[j][0] = __float_as_uint(v0); bb[j][1] = __float_as_uint(v1);
            }
#pragma unroll
            for (int i = 0; i < 4; i++)
#pragma unroll
                for (int j = 0; j < 4; j++)
                    mma_tf32(c[i][j], a[i][0], a[i][1], a[i][2], a[i][3],
                             bb[j][0], bb[j][1]);
        }
    }

    // ---- epilogue ----
#pragma unroll
    for (int i = 0; i < 4; i++) {
        int r0 = m0 + wm + i * 16 + tq;
        int r1 = r0 + 8;
        float bi0 = bias ? bias[r0] : 0.f;
        float bi1 = bias ? bias[r1] : 0.f;
#pragma unroll
        for (int j = 0; j < 4; j++) {
            int col = n0 + wn + j * 8 + tr * 2;
            float2 v0 = make_float2(c[i][j][0] + bi0, c[i][j][1] + bi0);
            float2 v1 = make_float2(c[i][j][2] + bi1, c[i][j][3] + bi1);
            if (roundC) {
                v0.x = f2tf32(v0.x); v0.y = f2tf32(v0.y);
                v1.x = f2tf32(v1.x); v1.y = f2tf32(v1.y);
            }
            *(float2*)(Cb + (size_t)r0 * ldc + col) = v0;
            *(float2*)(Cb + (size_t)r1 * ldc + col) = v1;
        }
    }
}

// ============================================================
extern "C" void kernel_launch(void* const* d_in, const int* in_sizes, int n_in,
                              void* d_out, int out_size)
{
    const float* x  = (const float*)d_in[0];
    const float* Wq = (const float*)d_in[1];
    const float* bq = (const float*)d_in[2];
    const float* Wk = (const float*)d_in[3];
    const float* bk = (const float*)d_in[4];
    const float* Wv = (const float*)d_in[5];
    const float* bv = (const float*)d_in[6];

    float* out = (float*)d_out;                   // (bs, d, n) raw layout
    float* att = out + (size_t)BS_ * N_ * D_;     // (bs, n, n)

    void* pV;
    cudaGetSymbolAddress(&pV, g_V);

    const int smem0 = STAGES * (A_STG + B0_STG) * 4;   // 61440 B
    const int smem1 = STAGES * (A_STG + B1_STG) * 4;   // 56832 B
    static bool attr_done = false;
    if (!attr_done) {
        cudaFuncSetAttribute(mm_tf32_kernel<0, 1, 1>,
                             cudaFuncAttributeMaxDynamicSharedMemorySize, smem0);
        cudaFuncSetAttribute(mm_tf32_kernel<1, 0, 1>,
                             cudaFuncAttributeMaxDynamicSharedMemorySize, smem1);
        attr_done = true;
    }

    qk_kernel<<<ROWS / 8, 256>>>(x, Wq, Wk, bq, bk);
    kminmax_kernel<<<BS_, 256>>>();
    softmax_kernel<<<ROWS / 8, 256>>>(att);

    // GEMM1: V[m,n] = sum_k Wv[m,k] x[n,k] + bv[m]
    //   grid.x = m-tiles (8), grid.y = n-tiles (256)
    mm_tf32_kernel<0, 1, 1><<<dim3(D_ / 128, ROWS / 128, 1), 256, smem0>>>(
        Wv, 1024, 0,
        x, 1024, 0,
        (float*)pV, ROWS, 0,
        bv, 1);

    // GEMM2: out[b][m,n] = sum_k V[m, b*1024+k] att[b][k,n]   (B n-major)
    mm_tf32_kernel<1, 0, 1><<<dim3(D_ / 128, N_ / 128, BS_), 256, smem1>>>(
        (const float*)pV, ROWS, 1024,
        att, 1024, (size_t)N_ * N_,
        out, 1024, (size_t)D_ * N_,
        nullptr, 0);
}